// round 11
// baseline (speedup 1.0000x reference)
#include <cuda_runtime.h>
#include <cuda_bf16.h>
#include <cuda_fp8.h>
#include <cfloat>
#include <cstdint>

// ---------------------------------------------------------------------------
// Problem constants
// ---------------------------------------------------------------------------
#define NTEST   16384
#define NTRAIN  16384
#define DIM     192
#define NCLASS  2
#define KNN     5

#define TM      64                  // test rows per CTA (2 CTAs/SM)
#define TN      128                 // train cols per tile
#define NTILES  (NTRAIN / TN)       // 128
#define KSTEPS  (DIM / 32)          // 6 mma k-steps (fp8: K=32 per step)
#define NTHREADS 256                // 8 warps: 2 (M) x 4 (N), warp tile 32x32
#define NCAND   16                  // top-16 kept per row (compact-thread regs)
#define NCAP    64                  // buffer depth == max inserts per 64-col phase

#define RSB     208                 // bytes per fp8 row in smem (192 + 16 pad)
#define TILEB   (TN * RSB)          // 26624 bytes per B tile (padded, contiguous)

// ---------------------------------------------------------------------------
// Global scratch (no cudaMalloc allowed)
// ---------------------------------------------------------------------------
__device__ float   g_ynorm[NTRAIN];
__device__ uint8_t g_A8[NTEST * DIM];            // H_test  e4m3, row-major 192B rows
__device__ uint8_t g_B8[NTILES * TILEB];         // H_train e4m3, tile-padded layout

// ---------------------------------------------------------------------------
// PTX helpers (base ISA: sm_89/sm_90 features, legal on sm_100 without 'a')
// ---------------------------------------------------------------------------
__device__ __forceinline__ uint32_t smem_u32(const void* p) {
    uint32_t a;
    asm("{ .reg .u64 t; cvta.to.shared.u64 t, %1; cvt.u32.u64 %0, t; }"
        : "=r"(a) : "l"(p));
    return a;
}

#define CP_ASYNC16(dst, src) \
    asm volatile("cp.async.cg.shared.global [%0], [%1], 16;" :: "r"(dst), "l"(src))
#define CP_COMMIT() asm volatile("cp.async.commit_group;" ::: "memory")
#define CP_WAIT0()  asm volatile("cp.async.wait_group 0;" ::: "memory")

#define MBAR_INIT(mb, n) \
    asm volatile("mbarrier.init.shared.b64 [%0], %1;" :: "r"((uint32_t)(mb)), "r"((uint32_t)(n)) : "memory")
#define MBAR_EXPECT_TX(mb, bytes) \
    asm volatile("mbarrier.arrive.expect_tx.shared.b64 _, [%0], %1;" :: "r"((uint32_t)(mb)), "r"((uint32_t)(bytes)) : "memory")
#define CP_BULK(dst, src, sz, mb) \
    asm volatile("cp.async.bulk.shared::cluster.global.mbarrier::complete_tx::bytes [%0], [%1], %2, [%3];" \
                 :: "r"((uint32_t)(dst)), "l"(src), "r"((uint32_t)(sz)), "r"((uint32_t)(mb)) : "memory")
#define FENCE_PROXY_ASYNC() asm volatile("fence.proxy.async.shared::cta;" ::: "memory")

#define MBAR_WAIT(mb, par) do {                                                     \
    uint32_t _mb = (uint32_t)(mb); uint32_t _p = (uint32_t)(par); uint32_t _done;   \
    asm volatile("{ .reg .pred p; mbarrier.try_wait.parity.acquire.cta.shared::cta.b64 p, [%1], %2; selp.b32 %0, 1, 0, p; }" \
                 : "=r"(_done) : "r"(_mb), "r"(_p) : "memory");                     \
    if (!_done) {                                                                   \
        asm volatile("{ .reg .pred P1; WL_%=: mbarrier.try_wait.parity.acquire.cta.shared::cta.b64 P1, [%0], %1, 0x989680; @P1 bra.uni WD_%=; bra.uni WL_%=; WD_%=: }" \
                     :: "r"(_mb), "r"(_p) : "memory");                              \
    }                                                                               \
} while (0)

#define LDMATRIX_X4(r0, r1, r2, r3, addr) \
    asm volatile("ldmatrix.sync.aligned.m8n8.x4.shared.b16 {%0,%1,%2,%3}, [%4];" \
                 : "=r"(r0), "=r"(r1), "=r"(r2), "=r"(r3) : "r"(addr))

__device__ __forceinline__ void mma_fp8(float* c,
                                        uint32_t a0, uint32_t a1, uint32_t a2, uint32_t a3,
                                        uint32_t b0, uint32_t b1) {
    asm volatile("mma.sync.aligned.m16n8k32.row.col.f32.e4m3.e4m3.f32 "
                 "{%0,%1,%2,%3}, {%4,%5,%6,%7}, {%8,%9}, {%0,%1,%2,%3};"
                 : "+f"(c[0]), "+f"(c[1]), "+f"(c[2]), "+f"(c[3])
                 : "r"(a0), "r"(a1), "r"(a2), "r"(a3), "r"(b0), "r"(b1));
}

// ---------------------------------------------------------------------------
// SMEM layout (bytes)  — total < 100 KB so 2 CTAs fit per SM
// ---------------------------------------------------------------------------
#define OFF_B        0                       // double buffer: +0 / +TILEB (53248)
#define OFF_A        (2 * TILEB)             // 53248, A: 64 rows x 208 B = 13312
#define OFF_THR      (OFF_A + TM * RSB)      // 66560  float [64]
#define OFF_CNT      (OFF_THR + 256)         // 66816  int   [64]
#define OFF_BUFD     (OFF_CNT + 256)         // 67072  float [64][NCAP] (16384)
#define OFF_BUFI     (OFF_BUFD + 16384)      // 83456  int   [64][NCAP] (16384)
#define OFF_MBAR     (OFF_BUFI + 16384)      // 99840  two 8B mbarriers
#define SMEM_BYTES   (OFF_MBAR + 16)         // 99856

// ---------------------------------------------------------------------------
// Prep kernel: one warp per row index w (< NTRAIN):
//  - Htrain[w] -> e4m3 into tile-padded g_B8, squared norm -> g_ynorm[w]
//  - Htest[w]  -> e4m3 into row-major g_A8
// ---------------------------------------------------------------------------
__device__ __forceinline__ uint32_t pack4_e4m3(float f0, float f1, float f2, float f3) {
    uint32_t b0 = __nv_cvt_float_to_fp8(f0, __NV_SATFINITE, __NV_E4M3);
    uint32_t b1 = __nv_cvt_float_to_fp8(f1, __NV_SATFINITE, __NV_E4M3);
    uint32_t b2 = __nv_cvt_float_to_fp8(f2, __NV_SATFINITE, __NV_E4M3);
    uint32_t b3 = __nv_cvt_float_to_fp8(f3, __NV_SATFINITE, __NV_E4M3);
    return b0 | (b1 << 8) | (b2 << 16) | (b3 << 24);
}

__global__ void prep_kernel(const float* __restrict__ Htest,
                            const float* __restrict__ Htrain) {
    int w    = (blockIdx.x * blockDim.x + threadIdx.x) >> 5;
    int lane = threadIdx.x & 31;
    if (w >= NTRAIN) return;

    const float4* tr = (const float4*)(Htrain + (size_t)w * DIM);  // 48 float4
    const float4* te = (const float4*)(Htest  + (size_t)w * DIM);
    uint32_t* ob = (uint32_t*)(g_B8 + (size_t)(w >> 7) * TILEB + (size_t)(w & 127) * RSB);
    uint32_t* oa = (uint32_t*)(g_A8 + (size_t)w * DIM);

    float s = 0.f;
    #pragma unroll
    for (int j = 0; j < 2; j++) {
        int c = lane + 32 * j;
        if (c < 48) {
            float4 b = tr[c];
            float4 a = te[c];
            s = fmaf(b.x, b.x, s); s = fmaf(b.y, b.y, s);
            s = fmaf(b.z, b.z, s); s = fmaf(b.w, b.w, s);
            ob[c] = pack4_e4m3(b.x, b.y, b.z, b.w);
            oa[c] = pack4_e4m3(a.x, a.y, a.z, a.w);
        }
    }
    #pragma unroll
    for (int o = 16; o; o >>= 1) s += __shfl_xor_sync(0xffffffffu, s, o);
    if (lane == 0) g_ynorm[w] = s;
}

// ---------------------------------------------------------------------------
// Main kernel: fp8 mma.sync (bulk-copied B), 2 CTAs/SM -> top-16 -> fp32 re-rank
// ---------------------------------------------------------------------------
__global__ __launch_bounds__(NTHREADS, 2)
void knn_mma_kernel(const float* __restrict__ Htest,
                    const float* __restrict__ Htrain,
                    const float* __restrict__ phat,
                    float* __restrict__ out) {
    extern __shared__ __align__(1024) char smem[];
    const uint32_t sbase = smem_u32(smem);
    const int tid   = threadIdx.x;
    const int wid   = tid >> 5;
    const int lid   = tid & 31;
    const int warpM = wid & 1;       // 0..1 -> rows warpM*32..+31
    const int warpN = wid >> 1;      // 0..3 -> cols warpN*32..+31
    const int m0    = blockIdx.x * TM;

    float* thr  = (float*)(smem + OFF_THR);
    int*   cnt  = (int*)  (smem + OFF_CNT);
    float* bufd = (float*)(smem + OFF_BUFD);
    int*   bufi = (int*)  (smem + OFF_BUFI);
    const uint32_t mbar0 = sbase + OFF_MBAR;
    const uint32_t mbar1 = sbase + OFF_MBAR + 8;

    // ---- prologue ----
    if (tid == 0) { MBAR_INIT(mbar0, 1); MBAR_INIT(mbar1, 1); }
    FENCE_PROXY_ASYNC();
    __syncthreads();

    if (tid == 0) {
        MBAR_EXPECT_TX(mbar0, TILEB);
        CP_BULK(sbase + OFF_B, (const char*)g_B8, TILEB, mbar0);
    }

    // A tile: 64 rows x 12 chunks of 16B via cp.async (one-time)
    #pragma unroll
    for (int it = 0; it < (TM * 12) / NTHREADS; it++) {
        int g  = tid + it * NTHREADS;        // 0..767
        int r  = g / 12;
        int ch = g % 12;
        CP_ASYNC16(sbase + OFF_A + r * RSB + ch * 16,
                   (const char*)g_A8 + (size_t)(m0 + r) * DIM + ch * 16);
    }
    CP_COMMIT();

    if (tid < TM) { thr[tid] = FLT_MAX; cnt[tid] = 0; }

    // private top-16 for the compact thread (row == tid, tid < TM)
    float pd[NCAND]; int pi[NCAND];
    #pragma unroll
    for (int i = 0; i < NCAND; i++) { pd[i] = FLT_MAX; pi[i] = -1; }

    CP_WAIT0();
    __syncthreads();

    const int lrow   = lid & 15;
    const int lchunk = lid >> 4;
    uint32_t a_addr[2];
    #pragma unroll
    for (int mf = 0; mf < 2; mf++)
        a_addr[mf] = sbase + OFF_A +
                     (warpM * 32 + mf * 16 + lrow) * RSB + lchunk * 16;

    const int erow0 = warpM * 32 + (lid >> 2);
    const int ecol0 = warpN * 32 + 2 * (lid & 3);

    // ---- main loop over B tiles ----
    for (int jt = 0; jt < NTILES; jt++) {
        const int cur = jt & 1;

        // next tile's bulk load (readers of buf[1-cur] finished at tile jt-1's
        // last barrier, which all threads passed before reaching here)
        if (tid == 0 && jt + 1 < NTILES) {
            uint32_t mb = (1 - cur) ? mbar1 : mbar0;
            MBAR_EXPECT_TX(mb, TILEB);
            CP_BULK(sbase + OFF_B + (1 - cur) * TILEB,
                    (const char*)g_B8 + (size_t)(jt + 1) * TILEB, TILEB, mb);
        }

        // refresh per-slot thresholds (registers) once per tile
        float thrR[4];
        #pragma unroll
        for (int s = 0; s < 4; s++)
            thrR[s] = thr[erow0 + (s >> 1) * 16 + (s & 1) * 8];

        MBAR_WAIT(cur ? mbar1 : mbar0, (jt >> 1) & 1);   // tile jt data ready

        // ---- 64x128x192 fp8 mma: warp tile 32x32, K=32 per step ----
        float acc[2][4][4];
        #pragma unroll
        for (int mf = 0; mf < 2; mf++)
            #pragma unroll
            for (int nf = 0; nf < 4; nf++)
                #pragma unroll
                for (int q = 0; q < 4; q++) acc[mf][nf][q] = 0.f;

        uint32_t b_base = sbase + OFF_B + cur * TILEB +
                          (warpN * 32 + lrow) * RSB + lchunk * 16;

        #pragma unroll
        for (int ks = 0; ks < KSTEPS; ks++) {
            const uint32_t ka = ks * 32;       // 32 fp8 per kstep
            uint32_t a[2][4], b[2][4];
            LDMATRIX_X4(a[0][0], a[0][1], a[0][2], a[0][3], a_addr[0] + ka);
            LDMATRIX_X4(a[1][0], a[1][1], a[1][2], a[1][3], a_addr[1] + ka);
            LDMATRIX_X4(b[0][0], b[0][1], b[0][2], b[0][3], b_base + ka);
            LDMATRIX_X4(b[1][0], b[1][1], b[1][2], b[1][3],
                        b_base + 16 * RSB + ka);
            #pragma unroll
            for (int mf = 0; mf < 2; mf++)
                #pragma unroll
                for (int nf = 0; nf < 4; nf++)
                    mma_fp8(acc[mf][nf],
                            a[mf][0], a[mf][1], a[mf][2], a[mf][3],
                            b[nf >> 1][nf & 1], b[nf >> 1][2 + (nf & 1)]);
        }

        // ---- epilogue: 2 phases x 64 cols/row; inserts <= NCAP structurally ----
        const int colbase = jt * TN;
        #pragma unroll
        for (int ph = 0; ph < 2; ph++) {
            #pragma unroll
            for (int nfp = 0; nfp < 2; nfp++) {
                const int nf   = ph * 2 + nfp;
                const int col0 = ecol0 + nf * 8;
                const int g0 = colbase + col0;
                const int g1 = g0 + 1;
                const float y0 = __ldg(&g_ynorm[g0]);
                const float y1 = __ldg(&g_ynorm[g1]);
                #pragma unroll
                for (int mf = 0; mf < 2; mf++) {
                    const float* cc = acc[mf][nf];
                    const int r0 = erow0 + mf * 16;
                    const int r1 = r0 + 8;
                    float d00 = fmaf(-2.f, cc[0], y0);
                    float d01 = fmaf(-2.f, cc[1], y1);
                    float d10 = fmaf(-2.f, cc[2], y0);
                    float d11 = fmaf(-2.f, cc[3], y1);
                    if (d00 < thrR[mf * 2]) {
                        int p = atomicAdd(&cnt[r0], 1);
                        bufd[r0*NCAP+p] = d00; bufi[r0*NCAP+p] = g0;
                    }
                    if (d01 < thrR[mf * 2]) {
                        int p = atomicAdd(&cnt[r0], 1);
                        bufd[r0*NCAP+p] = d01; bufi[r0*NCAP+p] = g1;
                    }
                    if (d10 < thrR[mf * 2 + 1]) {
                        int p = atomicAdd(&cnt[r1], 1);
                        bufd[r1*NCAP+p] = d10; bufi[r1*NCAP+p] = g0;
                    }
                    if (d11 < thrR[mf * 2 + 1]) {
                        int p = atomicAdd(&cnt[r1], 1);
                        bufd[r1*NCAP+p] = d11; bufi[r1*NCAP+p] = g1;
                    }
                }
            }
            __syncthreads();
            if (tid < TM) {
                int cn = cnt[tid];
                if (cn > 0) {
                    for (int i = 0; i < cn; i++) {
                        float d = bufd[tid * NCAP + i];
                        if (d < pd[NCAND - 1]) {
                            int idx = bufi[tid * NCAP + i];
                            int j = NCAND - 1;
                            while (j > 0 && pd[j - 1] > d) {
                                pd[j] = pd[j - 1]; pi[j] = pi[j - 1]; j--;
                            }
                            pd[j] = d; pi[j] = idx;
                        }
                    }
                    thr[tid] = pd[NCAND - 1];
                    cnt[tid] = 0;
                }
            }
            __syncthreads();
        }
    }

    // ---- dump candidates (reuse bufi region) ----
    int* cand = bufi;                          // [64][NCAND]
    if (tid < TM) {
        #pragma unroll
        for (int i = 0; i < NCAND; i++) cand[tid * NCAND + i] = pi[i];
    }
    __syncthreads();

    // ---- exact fp32 re-rank: warp per row, 16 candidates ----
    for (int r = wid; r < TM; r += 8) {
        const int rowg = m0 + r;
        const float* xrow = Htest + (size_t)rowg * DIM;
        float xv[6];
        #pragma unroll
        for (int j = 0; j < 6; j++) xv[j] = xrow[lid + 32 * j];

        float bd[KNN]; int bi[KNN];
        #pragma unroll
        for (int i = 0; i < KNN; i++) { bd[i] = FLT_MAX; bi[i] = 0x7fffffff; }

        for (int c = 0; c < NCAND; c++) {
            int idx = cand[r * NCAND + c];
            if (idx < 0) continue;
            const float* trow = Htrain + (size_t)idx * DIM;
            float s = 0.f;
            #pragma unroll
            for (int j = 0; j < 6; j++) s = fmaf(xv[j], trow[lid + 32 * j], s);
            #pragma unroll
            for (int o = 16; o; o >>= 1) s += __shfl_xor_sync(0xffffffffu, s, o);
            if (lid == 0) {
                float d = g_ynorm[idx] - 2.0f * s;
                int j = KNN;
                while (j > 0 && (d < bd[j - 1] ||
                                 (d == bd[j - 1] && idx < bi[j - 1]))) j--;
                if (j < KNN) {
                    for (int q = KNN - 1; q > j; q--) { bd[q] = bd[q-1]; bi[q] = bi[q-1]; }
                    bd[j] = d; bi[j] = idx;
                }
            }
        }
        if (lid == 0) {
            float s0 = 0.f, s1 = 0.f;
            #pragma unroll
            for (int i = 0; i < KNN; i++) {
                int idx = bi[i];
                s0 += phat[idx];
                s1 += phat[NTRAIN + idx];
            }
            out[rowg]         = s0 * (1.0f / KNN);
            out[NTEST + rowg] = s1 * (1.0f / KNN);
        }
    }
}

// ---------------------------------------------------------------------------
extern "C" void kernel_launch(void* const* d_in, const int* in_sizes, int n_in,
                              void* d_out, int out_size) {
    const float* Htest  = (const float*)d_in[0];
    const float* Htrain = (const float*)d_in[1];
    const float* phat   = (const float*)d_in[2];
    float* out = (float*)d_out;

    prep_kernel<<<(NTRAIN * 32) / 256, 256>>>(Htest, Htrain);

    cudaFuncSetAttribute(knn_mma_kernel,
                         cudaFuncAttributeMaxDynamicSharedMemorySize, SMEM_BYTES);
    knn_mma_kernel<<<NTEST / TM, NTHREADS, SMEM_BYTES>>>(Htest, Htrain, phat, out);
}

// round 12
// speedup vs baseline: 2.3208x; 2.3208x over previous
#include <cuda_runtime.h>
#include <cuda_bf16.h>
#include <cuda_fp8.h>
#include <cfloat>
#include <cstdint>

// ---------------------------------------------------------------------------
// Problem constants
// ---------------------------------------------------------------------------
#define NTEST   16384
#define NTRAIN  16384
#define DIM     192
#define NCLASS  2
#define KNN     5

#define TM      128                 // test rows per CTA
#define TN      128                 // train cols per tile
#define NTILES  (NTRAIN / TN)       // 128
#define KSTEPS  (DIM / 32)          // 6 mma k-steps (fp8: K=32 per step)
#define NTHREADS 512                // 16 warps: 4 (M) x 4 (N), warp tile 32x32
#define NSLOT   5                   // private top-5 per (thread,row-slot)
#define NOWN    16                  // owners per row
#define NDUMP   (NOWN * NSLOT)      // 80 candidates dumped per row
#define NCAND   16                  // compacted top-16 per row for re-rank

#define RSB     208                 // bytes per fp8 row in smem (192 + 16 pad)
#define TILEB   (TN * RSB)          // 26624 bytes per B tile

// ---------------------------------------------------------------------------
// Global scratch (no cudaMalloc allowed)
// ---------------------------------------------------------------------------
__device__ float   g_ynorm[NTRAIN];
__device__ uint8_t g_A8[NTEST * DIM];            // H_test  e4m3, row-major 192B rows
__device__ uint8_t g_B8[NTILES * TILEB];         // H_train e4m3, tile-padded layout

// ---------------------------------------------------------------------------
// PTX helpers (base ISA: sm_89/sm_90 features, legal on sm_100 without 'a')
// ---------------------------------------------------------------------------
__device__ __forceinline__ uint32_t smem_u32(const void* p) {
    uint32_t a;
    asm("{ .reg .u64 t; cvta.to.shared.u64 t, %1; cvt.u32.u64 %0, t; }"
        : "=r"(a) : "l"(p));
    return a;
}

#define CP_ASYNC16(dst, src) \
    asm volatile("cp.async.cg.shared.global [%0], [%1], 16;" :: "r"(dst), "l"(src))
#define CP_COMMIT() asm volatile("cp.async.commit_group;" ::: "memory")
#define CP_WAIT0()  asm volatile("cp.async.wait_group 0;" ::: "memory")

#define MBAR_INIT(mb, n) \
    asm volatile("mbarrier.init.shared.b64 [%0], %1;" :: "r"((uint32_t)(mb)), "r"((uint32_t)(n)) : "memory")
#define MBAR_EXPECT_TX(mb, bytes) \
    asm volatile("mbarrier.arrive.expect_tx.shared.b64 _, [%0], %1;" :: "r"((uint32_t)(mb)), "r"((uint32_t)(bytes)) : "memory")
#define CP_BULK(dst, src, sz, mb) \
    asm volatile("cp.async.bulk.shared::cluster.global.mbarrier::complete_tx::bytes [%0], [%1], %2, [%3];" \
                 :: "r"((uint32_t)(dst)), "l"(src), "r"((uint32_t)(sz)), "r"((uint32_t)(mb)) : "memory")
#define FENCE_PROXY_ASYNC() asm volatile("fence.proxy.async.shared::cta;" ::: "memory")

#define MBAR_WAIT(mb, par) do {                                                     \
    uint32_t _mb = (uint32_t)(mb); uint32_t _p = (uint32_t)(par); uint32_t _done;   \
    asm volatile("{ .reg .pred p; mbarrier.try_wait.parity.acquire.cta.shared::cta.b64 p, [%1], %2; selp.b32 %0, 1, 0, p; }" \
                 : "=r"(_done) : "r"(_mb), "r"(_p) : "memory");                     \
    if (!_done) {                                                                   \
        asm volatile("{ .reg .pred P1; WL_%=: mbarrier.try_wait.parity.acquire.cta.shared::cta.b64 P1, [%0], %1, 0x989680; @P1 bra.uni WD_%=; bra.uni WL_%=; WD_%=: }" \
                     :: "r"(_mb), "r"(_p) : "memory");                              \
    }                                                                               \
} while (0)

#define LDMATRIX_X4(r0, r1, r2, r3, addr) \
    asm volatile("ldmatrix.sync.aligned.m8n8.x4.shared.b16 {%0,%1,%2,%3}, [%4];" \
                 : "=r"(r0), "=r"(r1), "=r"(r2), "=r"(r3) : "r"(addr))

__device__ __forceinline__ void mma_fp8(float* c,
                                        uint32_t a0, uint32_t a1, uint32_t a2, uint32_t a3,
                                        uint32_t b0, uint32_t b1) {
    asm volatile("mma.sync.aligned.m16n8k32.row.col.f32.e4m3.e4m3.f32 "
                 "{%0,%1,%2,%3}, {%4,%5,%6,%7}, {%8,%9}, {%0,%1,%2,%3};"
                 : "+f"(c[0]), "+f"(c[1]), "+f"(c[2]), "+f"(c[3])
                 : "r"(a0), "r"(a1), "r"(a2), "r"(a3), "r"(b0), "r"(b1));
}

// ---------------------------------------------------------------------------
// Branchless sorted top-5 insert (ascending; index statics only — no spills)
// ---------------------------------------------------------------------------
#define INSERT5(sd, si, d, idx) do {                                          \
    if ((d) < sd[4]) {                                                        \
        bool c0 = (d) < sd[0], c1 = (d) < sd[1], c2 = (d) < sd[2], c3 = (d) < sd[3]; \
        sd[4] = c3 ? sd[3] : (d);          si[4] = c3 ? si[3] : (idx);        \
        sd[3] = c3 ? (c2 ? sd[2] : (d)) : sd[3]; si[3] = c3 ? (c2 ? si[2] : (idx)) : si[3]; \
        sd[2] = c2 ? (c1 ? sd[1] : (d)) : sd[2]; si[2] = c2 ? (c1 ? si[1] : (idx)) : si[2]; \
        sd[1] = c1 ? (c0 ? sd[0] : (d)) : sd[1]; si[1] = c1 ? (c0 ? si[0] : (idx)) : si[1]; \
        sd[0] = c0 ? (d) : sd[0];          si[0] = c0 ? (idx) : si[0];        \
    }                                                                         \
} while (0)

// ---------------------------------------------------------------------------
// SMEM layout (bytes)
// ---------------------------------------------------------------------------
#define OFF_B        0                       // double buffer: +0 / +TILEB (53248)
#define OFF_A        (2 * TILEB)             // 53248, A: 128 rows x 208B = 26624
#define OFF_DUMPD    (OFF_A + TM * RSB)      // 79872  float [128][NDUMP] (40960)
#define OFF_DUMPI    (OFF_DUMPD + TM*NDUMP*4)// 120832 int   [128][NDUMP] (40960)
#define OFF_C16      (OFF_DUMPI + TM*NDUMP*4)// 161792 int   [128][16]    (8192)
#define OFF_MBAR     (OFF_C16 + TM*NCAND*4)  // 169984 two 8B mbarriers
#define SMEM_BYTES   (OFF_MBAR + 16)         // 170000

// ---------------------------------------------------------------------------
// Prep kernel: one warp per row index w (< NTRAIN):
//  - Htrain[w] -> e4m3 into tile-padded g_B8, squared norm -> g_ynorm[w]
//  - Htest[w]  -> e4m3 into row-major g_A8
// ---------------------------------------------------------------------------
__device__ __forceinline__ uint32_t pack4_e4m3(float f0, float f1, float f2, float f3) {
    uint32_t b0 = __nv_cvt_float_to_fp8(f0, __NV_SATFINITE, __NV_E4M3);
    uint32_t b1 = __nv_cvt_float_to_fp8(f1, __NV_SATFINITE, __NV_E4M3);
    uint32_t b2 = __nv_cvt_float_to_fp8(f2, __NV_SATFINITE, __NV_E4M3);
    uint32_t b3 = __nv_cvt_float_to_fp8(f3, __NV_SATFINITE, __NV_E4M3);
    return b0 | (b1 << 8) | (b2 << 16) | (b3 << 24);
}

__global__ void prep_kernel(const float* __restrict__ Htest,
                            const float* __restrict__ Htrain) {
    int w    = (blockIdx.x * blockDim.x + threadIdx.x) >> 5;
    int lane = threadIdx.x & 31;
    if (w >= NTRAIN) return;

    const float4* tr = (const float4*)(Htrain + (size_t)w * DIM);  // 48 float4
    const float4* te = (const float4*)(Htest  + (size_t)w * DIM);
    uint32_t* ob = (uint32_t*)(g_B8 + (size_t)(w >> 7) * TILEB + (size_t)(w & 127) * RSB);
    uint32_t* oa = (uint32_t*)(g_A8 + (size_t)w * DIM);

    float s = 0.f;
    #pragma unroll
    for (int j = 0; j < 2; j++) {
        int c = lane + 32 * j;
        if (c < 48) {
            float4 b = tr[c];
            float4 a = te[c];
            s = fmaf(b.x, b.x, s); s = fmaf(b.y, b.y, s);
            s = fmaf(b.z, b.z, s); s = fmaf(b.w, b.w, s);
            ob[c] = pack4_e4m3(b.x, b.y, b.z, b.w);
            oa[c] = pack4_e4m3(a.x, a.y, a.z, a.w);
        }
    }
    #pragma unroll
    for (int o = 16; o; o >>= 1) s += __shfl_xor_sync(0xffffffffu, s, o);
    if (lane == 0) g_ynorm[w] = s;
}

// ---------------------------------------------------------------------------
// Main kernel: fp8 mma.sync, barrier-free private top-5 -> compact -> re-rank
// ---------------------------------------------------------------------------
__global__ __launch_bounds__(NTHREADS, 1)
void knn_mma_kernel(const float* __restrict__ Htest,
                    const float* __restrict__ Htrain,
                    const float* __restrict__ phat,
                    float* __restrict__ out) {
    extern __shared__ __align__(1024) char smem[];
    const uint32_t sbase = smem_u32(smem);
    const int tid   = threadIdx.x;
    const int wid   = tid >> 5;
    const int lid   = tid & 31;
    const int warpM = wid & 3;       // 0..3 -> rows warpM*32..+31
    const int warpN = wid >> 2;      // 0..3 -> cols warpN*32..+31
    const int m0    = blockIdx.x * TM;

    float* dumpd = (float*)(smem + OFF_DUMPD);
    int*   dumpi = (int*)  (smem + OFF_DUMPI);
    int*   c16   = (int*)  (smem + OFF_C16);
    const uint32_t mbar0 = sbase + OFF_MBAR;
    const uint32_t mbar1 = sbase + OFF_MBAR + 8;

    // ---- prologue ----
    if (tid == 0) { MBAR_INIT(mbar0, 1); MBAR_INIT(mbar1, 1); }
    FENCE_PROXY_ASYNC();
    __syncthreads();

    if (tid == 0) {
        MBAR_EXPECT_TX(mbar0, TILEB);
        CP_BULK(sbase + OFF_B, (const char*)g_B8, TILEB, mbar0);
    }

    // A tile: 128 rows x 12 chunks of 16B via cp.async (one-time)
    #pragma unroll
    for (int it = 0; it < (TM * 12) / NTHREADS; it++) {
        int g  = tid + it * NTHREADS;
        int r  = g / 12;
        int ch = g % 12;
        CP_ASYNC16(sbase + OFF_A + r * RSB + ch * 16,
                   (const char*)g_A8 + (size_t)(m0 + r) * DIM + ch * 16);
    }
    CP_COMMIT();
    CP_WAIT0();
    __syncthreads();

    const int lrow   = lid & 15;
    const int lchunk = lid >> 4;
    uint32_t a_addr[2];
    #pragma unroll
    for (int mf = 0; mf < 2; mf++)
        a_addr[mf] = sbase + OFF_A +
                     (warpM * 32 + mf * 16 + lrow) * RSB + lchunk * 16;

    const int ecol0 = warpN * 32 + 2 * (lid & 3);

    // ---- private selection: 4 row-slots, branchless top-5 each ----
    float sd0[NSLOT], sd1[NSLOT], sd2[NSLOT], sd3[NSLOT];
    int   si0[NSLOT], si1[NSLOT], si2[NSLOT], si3[NSLOT];
    #pragma unroll
    for (int i = 0; i < NSLOT; i++) {
        sd0[i] = FLT_MAX; sd1[i] = FLT_MAX; sd2[i] = FLT_MAX; sd3[i] = FLT_MAX;
        si0[i] = -1; si1[i] = -1; si2[i] = -1; si3[i] = -1;
    }

    // ---- main loop over B tiles: 1 barrier + 1 mbar-wait per tile ----
    for (int jt = 0; jt < NTILES; jt++) {
        const int cur = jt & 1;

        if (tid == 0 && jt + 1 < NTILES) {
            uint32_t mb = (1 - cur) ? mbar1 : mbar0;
            MBAR_EXPECT_TX(mb, TILEB);
            CP_BULK(sbase + OFF_B + (1 - cur) * TILEB,
                    (const char*)g_B8 + (size_t)(jt + 1) * TILEB, TILEB, mb);
        }

        MBAR_WAIT(cur ? mbar1 : mbar0, (jt >> 1) & 1);   // tile jt data ready

        // ---- 128x128x192 fp8 mma: warp tile 32x32 ----
        float acc[2][4][4];
        #pragma unroll
        for (int mf = 0; mf < 2; mf++)
            #pragma unroll
            for (int nf = 0; nf < 4; nf++)
                #pragma unroll
                for (int q = 0; q < 4; q++) acc[mf][nf][q] = 0.f;

        uint32_t b_base = sbase + OFF_B + cur * TILEB +
                          (warpN * 32 + lrow) * RSB + lchunk * 16;

        #pragma unroll
        for (int ks = 0; ks < KSTEPS; ks++) {
            const uint32_t ka = ks * 32;
            uint32_t a[2][4], b[2][4];
            LDMATRIX_X4(a[0][0], a[0][1], a[0][2], a[0][3], a_addr[0] + ka);
            LDMATRIX_X4(a[1][0], a[1][1], a[1][2], a[1][3], a_addr[1] + ka);
            LDMATRIX_X4(b[0][0], b[0][1], b[0][2], b[0][3], b_base + ka);
            LDMATRIX_X4(b[1][0], b[1][1], b[1][2], b[1][3],
                        b_base + 16 * RSB + ka);
            #pragma unroll
            for (int mf = 0; mf < 2; mf++)
                #pragma unroll
                for (int nf = 0; nf < 4; nf++)
                    mma_fp8(acc[mf][nf],
                            a[mf][0], a[mf][1], a[mf][2], a[mf][3],
                            b[nf >> 1][nf & 1], b[nf >> 1][2 + (nf & 1)]);
        }

        // ---- epilogue: fully private, no atomics, no barriers ----
        const int colbase = jt * TN;
        #pragma unroll
        for (int nf = 0; nf < 4; nf++) {
            const int g0 = colbase + ecol0 + nf * 8;
            const int g1 = g0 + 1;
            const float y0 = __ldg(&g_ynorm[g0]);
            const float y1 = __ldg(&g_ynorm[g1]);
            {   // mf = 0: slots 0 (row+0) and 1 (row+8)
                const float* cc = acc[0][nf];
                float d00 = fmaf(-2.f, cc[0], y0);
                float d01 = fmaf(-2.f, cc[1], y1);
                float d10 = fmaf(-2.f, cc[2], y0);
                float d11 = fmaf(-2.f, cc[3], y1);
                INSERT5(sd0, si0, d00, g0);
                INSERT5(sd0, si0, d01, g1);
                INSERT5(sd1, si1, d10, g0);
                INSERT5(sd1, si1, d11, g1);
            }
            {   // mf = 1: slots 2 and 3
                const float* cc = acc[1][nf];
                float d00 = fmaf(-2.f, cc[0], y0);
                float d01 = fmaf(-2.f, cc[1], y1);
                float d10 = fmaf(-2.f, cc[2], y0);
                float d11 = fmaf(-2.f, cc[3], y1);
                INSERT5(sd2, si2, d00, g0);
                INSERT5(sd2, si2, d01, g1);
                INSERT5(sd3, si3, d10, g0);
                INSERT5(sd3, si3, d11, g1);
            }
        }
        __syncthreads();   // all reads of buf[cur] done before jt+1 overwrite
    }

    // ---- dump: 16 owners x 5 candidates per row ----
    {
        const int owner = warpN * 4 + (lid & 3);           // 0..15
        const int rbase = warpM * 32 + (lid >> 2);
        #pragma unroll
        for (int i = 0; i < NSLOT; i++) {
            dumpd[(rbase +  0) * NDUMP + owner * NSLOT + i] = sd0[i];
            dumpi[(rbase +  0) * NDUMP + owner * NSLOT + i] = si0[i];
            dumpd[(rbase +  8) * NDUMP + owner * NSLOT + i] = sd1[i];
            dumpi[(rbase +  8) * NDUMP + owner * NSLOT + i] = si1[i];
            dumpd[(rbase + 16) * NDUMP + owner * NSLOT + i] = sd2[i];
            dumpi[(rbase + 16) * NDUMP + owner * NSLOT + i] = si2[i];
            dumpd[(rbase + 24) * NDUMP + owner * NSLOT + i] = sd3[i];
            dumpi[(rbase + 24) * NDUMP + owner * NSLOT + i] = si3[i];
        }
    }
    __syncthreads();

    // ---- compact: one thread per row selects top-16 of the 80 ----
    if (tid < TM) {
        float pd[NCAND]; int pi[NCAND];
        #pragma unroll
        for (int i = 0; i < NCAND; i++) { pd[i] = FLT_MAX; pi[i] = -1; }
        for (int i = 0; i < NDUMP; i++) {
            float d = dumpd[tid * NDUMP + i];
            if (d < pd[NCAND - 1]) {
                int idx = dumpi[tid * NDUMP + i];
                int j = NCAND - 1;
                while (j > 0 && pd[j - 1] > d) {
                    pd[j] = pd[j - 1]; pi[j] = pi[j - 1]; j--;
                }
                pd[j] = d; pi[j] = idx;
            }
        }
        #pragma unroll
        for (int i = 0; i < NCAND; i++) c16[tid * NCAND + i] = pi[i];
    }
    __syncthreads();

    // ---- exact fp32 re-rank: warp per row, 16 candidates ----
    for (int r = wid; r < TM; r += 16) {
        const int rowg = m0 + r;
        const float* xrow = Htest + (size_t)rowg * DIM;
        float xv[6];
        #pragma unroll
        for (int j = 0; j < 6; j++) xv[j] = xrow[lid + 32 * j];

        float bd[KNN]; int bi[KNN];
        #pragma unroll
        for (int i = 0; i < KNN; i++) { bd[i] = FLT_MAX; bi[i] = 0x7fffffff; }

        for (int c = 0; c < NCAND; c++) {
            int idx = c16[r * NCAND + c];
            if (idx < 0) continue;
            const float* trow = Htrain + (size_t)idx * DIM;
            float s = 0.f;
            #pragma unroll
            for (int j = 0; j < 6; j++) s = fmaf(xv[j], trow[lid + 32 * j], s);
            #pragma unroll
            for (int o = 16; o; o >>= 1) s += __shfl_xor_sync(0xffffffffu, s, o);
            if (lid == 0) {
                float d = g_ynorm[idx] - 2.0f * s;
                int j = KNN;
                while (j > 0 && (d < bd[j - 1] ||
                                 (d == bd[j - 1] && idx < bi[j - 1]))) j--;
                if (j < KNN) {
                    for (int q = KNN - 1; q > j; q--) { bd[q] = bd[q-1]; bi[q] = bi[q-1]; }
                    bd[j] = d; bi[j] = idx;
                }
            }
        }
        if (lid == 0) {
            float s0 = 0.f, s1 = 0.f;
            #pragma unroll
            for (int i = 0; i < KNN; i++) {
                int idx = bi[i];
                s0 += phat[idx];
                s1 += phat[NTRAIN + idx];
            }
            out[rowg]         = s0 * (1.0f / KNN);
            out[NTEST + rowg] = s1 * (1.0f / KNN);
        }
    }
}

// ---------------------------------------------------------------------------
extern "C" void kernel_launch(void* const* d_in, const int* in_sizes, int n_in,
                              void* d_out, int out_size) {
    const float* Htest  = (const float*)d_in[0];
    const float* Htrain = (const float*)d_in[1];
    const float* phat   = (const float*)d_in[2];
    float* out = (float*)d_out;

    prep_kernel<<<(NTRAIN * 32) / 256, 256>>>(Htest, Htrain);

    cudaFuncSetAttribute(knn_mma_kernel,
                         cudaFuncAttributeMaxDynamicSharedMemorySize, SMEM_BYTES);
    knn_mma_kernel<<<NTEST / TM, NTHREADS, SMEM_BYTES>>>(Htest, Htrain, phat, out);
}